// round 9
// baseline (speedup 1.0000x reference)
#include <cuda_runtime.h>
#include <cuda_bf16.h>
#include <math.h>

#define NB    4
#define NPTS  2048
#define CDIM  256
#define DFFN  1024
#define NHEAD 4
#define NKNN  16
#define MTOK  (NB*NPTS)   // 8192

typedef unsigned short ushort_t;

// weight-split segment offsets (elements)
#define W_P    0
#define W_QKV  65536
#define W_O    262144
#define W_1    327680
#define W_2    589824
#define W_TOT  851968

// ---------------- scratch ----------------
__device__ __align__(16) ushort_t g_th[2*MTOK*CDIM];
__device__ __align__(16) ushort_t g_tl[2*MTOK*CDIM];
__device__ __align__(16) float    g_x [2*MTOK*CDIM];
__device__ __align__(16) ushort_t g_xh[2*MTOK*CDIM];
__device__ __align__(16) ushort_t g_xl[2*MTOK*CDIM];
__device__ __align__(16) float    g_q [MTOK*CDIM];
__device__ __align__(16) float    g_kv[MTOK*512];
__device__ __align__(16) ushort_t g_aoh[MTOK*CDIM];
__device__ __align__(16) ushort_t g_aol[MTOK*CDIM];
__device__ __align__(16) float    g_tp[MTOK*CDIM];
__device__ __align__(16) ushort_t g_yh[MTOK*CDIM];
__device__ __align__(16) ushort_t g_yl[MTOK*CDIM];
__device__ __align__(16) ushort_t g_hh[MTOK*DFFN];
__device__ __align__(16) ushort_t g_hl[MTOK*DFFN];
__device__ __align__(16) ushort_t g_wh[W_TOT];
__device__ __align__(16) ushort_t g_wl[W_TOT];
__device__ __align__(16) int      g_idx[MTOK*NKNN];
__device__ __align__(16) float    g_bv [MTOK*NKNN];

__device__ __forceinline__ float gelu_exact(float x) {
    return 0.5f * x * (1.0f + erff(x * 0.70710678118654752440f));
}

#define CP_ASYNC16(smem_u32, gptr) \
    asm volatile("cp.async.cg.shared.global [%0], [%1], 16;" :: "r"(smem_u32), "l"(gptr))

#define LDSM4(R, addr) \
    asm volatile("ldmatrix.sync.aligned.m8n8.x4.shared.b16 {%0,%1,%2,%3}, [%4];" \
        : "=r"((R)[0]), "=r"((R)[1]), "=r"((R)[2]), "=r"((R)[3]) : "r"(addr))

// split a float into bf16 hi (truncate) + bf16 lo (rn); lo = x - hi is exact in fp32
__device__ __forceinline__ void split1(float x, ushort_t& h, ushort_t& l) {
    unsigned r = __float_as_uint(x);
    h = (ushort_t)(r >> 16);
    float lo = x - __uint_as_float(r & 0xffff0000u);
    __nv_bfloat16 lb = __float2bfloat16(lo);
    l = *reinterpret_cast<unsigned short*>(&lb);
}
// split a pair -> packed words (hi word: x0 low half, x1 high half; same for lo)
__device__ __forceinline__ void split_pair(float x0, float x1, unsigned& hi, unsigned& lo) {
    unsigned r0 = __float_as_uint(x0), r1 = __float_as_uint(x1);
    asm("prmt.b32 %0, %1, %2, 0x7632;" : "=r"(hi) : "r"(r0), "r"(r1));
    float l0 = x0 - __uint_as_float(r0 & 0xffff0000u);
    float l1 = x1 - __uint_as_float(r1 & 0xffff0000u);
    asm("cvt.rn.bf16x2.f32 %0, %1, %2;" : "=r"(lo) : "f"(l1), "f"(l0));
}
__device__ __forceinline__ float bfh(ushort_t h) { return __uint_as_float(((unsigned)h) << 16); }

// ---------------- weight split prep ----------------
__global__ void split_weights(const float* __restrict__ Wp, const float* __restrict__ Wqkv,
                              const float* __restrict__ Wo, const float* __restrict__ W1,
                              const float* __restrict__ W2,
                              ushort_t* __restrict__ wh, ushort_t* __restrict__ wl) {
    int i = blockIdx.x * 256 + threadIdx.x;
    if (i >= W_TOT) return;
    const float* src; int off;
    if      (i < W_QKV) { src = Wp;   off = i; }
    else if (i < W_O)   { src = Wqkv; off = i - W_QKV; }
    else if (i < W_1)   { src = Wo;   off = i - W_O; }
    else if (i < W_2)   { src = W1;   off = i - W_1; }
    else                { src = W2;   off = i - W_2; }
    split1(src[off], wh[i], wl[i]);
}

// ---------------- fused transpose (B,C,N) -> (B,N,C), split bf16 out ----------------
__global__ void transpose_kernel(const float* __restrict__ src1, const float* __restrict__ src2,
                                 ushort_t* __restrict__ oh, ushort_t* __restrict__ ol) {
    __shared__ float t[32][33];
    int z = blockIdx.z;
    const float* in = (z < 4) ? src1 : src2;
    int b = z & 3;
    size_t dbase = (size_t)(z < 4 ? 0 : MTOK * CDIM) + (size_t)b * NPTS * CDIM;
    const float* sp = in + (size_t)b * CDIM * NPTS;
    int n0 = blockIdx.x * 32, c0 = blockIdx.y * 32;
    int tx = threadIdx.x, ty = threadIdx.y;
#pragma unroll
    for (int i = 0; i < 4; i++)
        t[ty + 8 * i][tx] = sp[(size_t)(c0 + ty + 8 * i) * NPTS + n0 + tx];
    __syncthreads();
#pragma unroll
    for (int i = 0; i < 4; i++) {
        size_t o = dbase + (size_t)(n0 + ty + 8 * i) * CDIM + c0 + tx;
        split1(t[tx][ty + 8 * i], oh[o], ol[o]);
    }
}

// ---------------- bf16x3 tensor-core GEMM, pre-split A and W ----------------
// out[m,n] = epi( sum_k A[m,k]*W[n,k] + bias[n] )
// CTA 64x64x16, 128 thr; warp tile 16m x 64n; ldmatrix + mma.m16n8k16.bf16 x3 terms.
// MODE 0: fp32 out    MODE 1: gelu -> split bf16 out    MODE 2: + res(split), transposed fp32 out
#define SROWB 48   // smem row stride in bytes (24 bf16; 16 used) - conflict-free LDSM
#define TILEB 3072 // 64 * 48

template <int MODE>
__global__ void __launch_bounds__(128) mma_gemm(
        const ushort_t* __restrict__ Ah, const ushort_t* __restrict__ Al,
        const ushort_t* __restrict__ Wh, const ushort_t* __restrict__ Wl,
        const float* __restrict__ bias,
        const ushort_t* __restrict__ resh, const ushort_t* __restrict__ resl,
        float* __restrict__ out32, ushort_t* __restrict__ outh, ushort_t* __restrict__ outl,
        int M, int N, int K) {
    __shared__ ushort_t sm[2][4][64 * 24];   // [buf][Ah,Al,Bh,Bl]
    const int tid = threadIdx.x;
    const int lane = tid & 31, warp = tid >> 5;
    const int g = lane >> 2, tig = lane & 3;
    const int m0 = blockIdx.y * 64, n0 = blockIdx.x * 64;

    const int lrow = tid >> 1, lh = tid & 1;
    const ushort_t* Ahg = Ah + (size_t)(m0 + lrow) * K + lh * 8;
    const ushort_t* Alg = Al + (size_t)(m0 + lrow) * K + lh * 8;
    const ushort_t* Whg = Wh + (size_t)(n0 + lrow) * K + lh * 8;
    const ushort_t* Wlg = Wl + (size_t)(n0 + lrow) * K + lh * 8;
    const unsigned smb = (unsigned)__cvta_generic_to_shared(&sm[0][0][0]);
    const unsigned wr = (unsigned)(lrow * SROWB + lh * 16);

    // ldmatrix lane addresses (within-tile byte offsets)
    const unsigned aoff = (unsigned)((warp * 16 + (lane & 15)) * SROWB + (lane >> 4) * 16);
    const unsigned boff = (unsigned)((((lane >> 4) & 1) * 8 + (lane & 7)) * SROWB + ((lane >> 3) & 1) * 16);

    float c[8][4];
#pragma unroll
    for (int i = 0; i < 8; i++)
#pragma unroll
        for (int j = 0; j < 4; j++) c[i][j] = 0.0f;

    const int nIter = K / 16;
    {
        CP_ASYNC16(smb + 0 * TILEB + wr, Ahg);
        CP_ASYNC16(smb + 1 * TILEB + wr, Alg);
        CP_ASYNC16(smb + 2 * TILEB + wr, Whg);
        CP_ASYNC16(smb + 3 * TILEB + wr, Wlg);
        asm volatile("cp.async.commit_group;");
    }

    for (int kt = 0; kt < nIter; kt++) {
        asm volatile("cp.async.wait_group 0;");
        __syncthreads();
        const int buf = kt & 1;
        if (kt + 1 < nIter) {
            const int k1 = (kt + 1) * 16;
            const unsigned d = smb + (buf ^ 1) * 4 * TILEB + wr;
            CP_ASYNC16(d + 0 * TILEB, Ahg + k1);
            CP_ASYNC16(d + 1 * TILEB, Alg + k1);
            CP_ASYNC16(d + 2 * TILEB, Whg + k1);
            CP_ASYNC16(d + 3 * TILEB, Wlg + k1);
            asm volatile("cp.async.commit_group;");
        }
        const unsigned base = smb + buf * 4 * TILEB;
        unsigned AH[4], AL[4];
        LDSM4(AH, base + 0 * TILEB + aoff);
        LDSM4(AL, base + 1 * TILEB + aoff);
#pragma unroll
        for (int p = 0; p < 4; p++) {
            unsigned BH[4], BL[4];
            LDSM4(BH, base + 2 * TILEB + boff + p * 16 * SROWB);
            LDSM4(BL, base + 3 * TILEB + boff + p * 16 * SROWB);
#define MMA_BF16(CC, A0,A1,A2,A3, B0,B1) \
    asm volatile("mma.sync.aligned.m16n8k16.row.col.f32.bf16.bf16.f32 " \
        "{%0,%1,%2,%3}, {%4,%5,%6,%7}, {%8,%9}, {%0,%1,%2,%3};" \
        : "+f"((CC)[0]), "+f"((CC)[1]), "+f"((CC)[2]), "+f"((CC)[3]) \
        : "r"(A0), "r"(A1), "r"(A2), "r"(A3), "r"(B0), "r"(B1))
            MMA_BF16(c[2*p],   AH[0],AH[1],AH[2],AH[3], BL[0],BL[1]);
            MMA_BF16(c[2*p],   AL[0],AL[1],AL[2],AL[3], BH[0],BH[1]);
            MMA_BF16(c[2*p],   AH[0],AH[1],AH[2],AH[3], BH[0],BH[1]);
            MMA_BF16(c[2*p+1], AH[0],AH[1],AH[2],AH[3], BL[2],BL[3]);
            MMA_BF16(c[2*p+1], AL[0],AL[1],AL[2],AL[3], BH[2],BH[3]);
            MMA_BF16(c[2*p+1], AH[0],AH[1],AH[2],AH[3], BH[2],BH[3]);
#undef MMA_BF16
        }
        __syncthreads();
    }

    // epilogue
#pragma unroll
    for (int nt = 0; nt < 8; nt++) {
        int col = n0 + nt * 8 + tig * 2;
        float b0 = bias[col], b1 = bias[col + 1];
#pragma unroll
        for (int half = 0; half < 2; half++) {
            int m = m0 + warp * 16 + g + half * 8;
            float v0 = c[nt][half * 2 + 0] + b0;
            float v1 = c[nt][half * 2 + 1] + b1;
            if (MODE == 1) {
                v0 = gelu_exact(v0); v1 = gelu_exact(v1);
                unsigned hw, lw;
                split_pair(v0, v1, hw, lw);
                *reinterpret_cast<unsigned*>(outh + (size_t)m * N + col) = hw;
                *reinterpret_cast<unsigned*>(outl + (size_t)m * N + col) = lw;
            } else if (MODE == 2) {
                unsigned uh = *reinterpret_cast<const unsigned*>(resh + (size_t)m * CDIM + col);
                unsigned ul = *reinterpret_cast<const unsigned*>(resl + (size_t)m * CDIM + col);
                v0 += __uint_as_float(uh << 16) + __uint_as_float(ul << 16);
                v1 += __uint_as_float(uh & 0xffff0000u) + __uint_as_float(ul & 0xffff0000u);
                int b = m >> 11, nn = m & (NPTS - 1);
                out32[((size_t)b * CDIM + col) * NPTS + nn]     = v0;
                out32[((size_t)b * CDIM + col + 1) * NPTS + nn] = v1;
            } else {
                *reinterpret_cast<float2*>(out32 + (size_t)m * N + col) = make_float2(v0, v1);
            }
        }
    }
}

// ---------------- LayerNorm: warp per row; in = fp32 OR split; out = split ----------------
__global__ void ln2_kernel(const float* __restrict__ x32,
                           const ushort_t* __restrict__ xh, const ushort_t* __restrict__ xl,
                           const float* __restrict__ res,
                           const float* __restrict__ g, const float* __restrict__ be,
                           ushort_t* __restrict__ oh, ushort_t* __restrict__ ol) {
    int warp = threadIdx.x >> 5, lane = threadIdx.x & 31;
    size_t row = (size_t)blockIdx.x * 8 + warp;
    float v[8], s = 0.0f, s2 = 0.0f;
#pragma unroll
    for (int i = 0; i < 8; i++) {
        size_t o = row * CDIM + i * 32 + lane;
        v[i] = x32 ? x32[o] : (bfh(xh[o]) + bfh(xl[o]));
        if (res) v[i] += res[o];
        s += v[i]; s2 += v[i] * v[i];
    }
#pragma unroll
    for (int o = 16; o > 0; o >>= 1) {
        s  += __shfl_xor_sync(0xffffffffu, s, o);
        s2 += __shfl_xor_sync(0xffffffffu, s2, o);
    }
    float mean = s * (1.0f / 256.0f);
    float var  = s2 * (1.0f / 256.0f) - mean * mean;
    float rstd = rsqrtf(var + 1e-5f);
#pragma unroll
    for (int i = 0; i < 8; i++) {
        size_t o = row * CDIM + i * 32 + lane;
        float y = (v[i] - mean) * rstd * g[i * 32 + lane] + be[i * 32 + lane];
        split1(y, oh[o], ol[o]);
    }
}

// ---------------- KNN top-16 via exact 4-round radix select + rel-pos bias MLP ----------------
#define TIECAP 128
__global__ void knn_kernel(const float* __restrict__ pos,
                           const float* __restrict__ Wr1, const float* __restrict__ br1,
                           const float* __restrict__ Wr2, const float* __restrict__ br2,
                           int* __restrict__ idx_out, float* __restrict__ bias_out) {
    __shared__ unsigned long long keys[NPTS];
    __shared__ int hist[256];
    __shared__ int sel[NKNN];
    __shared__ int tiebuf[TIECAP];
    __shared__ int cnts[2];
    __shared__ unsigned sh_prefix;
    __shared__ int sh_krem;
    int bq = blockIdx.x;
    int b = bq >> 11, i = bq & (NPTS - 1);
    int t = threadIdx.x;
    const float* P = pos + (size_t)b * 3 * NPTS;
    float xi = P[i], yi = P[NPTS + i], zi = P[2 * NPTS + i];
    float sqi = xi * xi + yi * yi + zi * zi;
    for (int j = t; j < NPTS; j += 256) {
        float xj = P[j], yj = P[NPTS + j], zj = P[2 * NPTS + j];
        float sqj = xj * xj + yj * yj + zj * zj;
        float dot = xi * xj + yi * yj + zi * zj;
        float dist = sqi + sqj - 2.0f * dot;
        unsigned db = __float_as_uint(dist);
        db = (db & 0x80000000u) ? ~db : (db | 0x80000000u);
        keys[j] = ((unsigned long long)db << 32) | (unsigned)j;
    }
    if (t == 0) { cnts[0] = 0; cnts[1] = 0; }

    unsigned prefix = 0;
    int krem = NKNN;
#pragma unroll
    for (int r = 0; r < 4; r++) {
        const int shift = 24 - 8 * r;
        hist[t] = 0;
        __syncthreads();
        for (int j = t; j < NPTS; j += 256) {
            unsigned d32 = (unsigned)(keys[j] >> 32);
            bool match = (r == 0) || ((d32 >> (shift + 8)) == (prefix >> (shift + 8)));
            if (match) {
                int digit = (d32 >> shift) & 0xFF;
                unsigned mask = __match_any_sync(__activemask(), digit);
                int leader = __ffs(mask) - 1;
                if ((int)(t & 31) == leader) atomicAdd(&hist[digit], __popc(mask));
            }
        }
        __syncthreads();
        if (t < 32) {
            int loc[8], s = 0;
#pragma unroll
            for (int u = 0; u < 8; u++) { loc[u] = s; s += hist[t * 8 + u]; }
            int run = s;
#pragma unroll
            for (int o = 1; o < 32; o <<= 1) {
                int v = __shfl_up_sync(0xffffffffu, run, o);
                if (t >= o) run += v;
            }
            int excl = run - s;
#pragma unroll
            for (int u = 0; u < 8; u++) {
                int below = excl + loc[u];
                int c = hist[t * 8 + u];
                if (below < krem && krem <= below + c) {
                    sh_prefix = prefix | ((unsigned)(t * 8 + u) << shift);
                    sh_krem = krem - below;
                }
            }
        }
        __syncthreads();
        prefix = sh_prefix;
        krem = sh_krem;
        __syncthreads();
    }

    for (int j = t; j < NPTS; j += 256) {
        unsigned d32 = (unsigned)(keys[j] >> 32);
        if (d32 < prefix) {
            int p = atomicAdd(&cnts[0], 1);
            sel[p] = j;
        } else if (d32 == prefix) {
            int p = atomicAdd(&cnts[1], 1);
            if (p < TIECAP) tiebuf[p] = j;
        }
    }
    __syncthreads();
    if (t == 0) {
        int na = cnts[0];
        int nt = cnts[1] < TIECAP ? cnts[1] : TIECAP;
        for (int a = 1; a < na; a++) {
            int v = sel[a], p = a - 1;
            while (p >= 0 && sel[p] > v) { sel[p + 1] = sel[p]; p--; }
            sel[p + 1] = v;
        }
        for (int s = 0; s < NKNN - na; s++) {
            int bestv = 1 << 30, bi = 0;
            for (int u = 0; u < nt; u++)
                if (tiebuf[u] < bestv) { bestv = tiebuf[u]; bi = u; }
            sel[na + s] = bestv;
            tiebuf[bi] = 1 << 30;
        }
    }
    __syncthreads();

    if (t < NKNN) {
        int j = sel[t];
        float rx = xi - P[j], ry = yi - P[NPTS + j], rz = zi - P[2 * NPTS + j];
        float acc = 0.0f;
#pragma unroll 8
        for (int o = 0; o < 64; o++) {
            float hp = Wr1[o * 3] * rx + Wr1[o * 3 + 1] * ry + Wr1[o * 3 + 2] * rz + br1[o];
            acc += Wr2[o] * gelu_exact(hp);
        }
        idx_out[(size_t)bq * NKNN + t] = j;
        bias_out[(size_t)bq * NKNN + t] = acc + br2[0];
    }
}

// ---------------- sparse attention (kv packed: row = [k(256) | v(256)]); split out ----------
__global__ void attn_kernel(const float* __restrict__ q, const float* __restrict__ kv,
                            const int* __restrict__ idx, const float* __restrict__ bias,
                            ushort_t* __restrict__ oh, ushort_t* __restrict__ ol) {
    __shared__ int   sj[NKNN];
    __shared__ float sb[NKNN];
    int m = blockIdx.x;
    int b = m >> 11;
    int warp = threadIdx.x >> 5, lane = threadIdx.x & 31;
    if (threadIdx.x < NKNN) {
        sj[threadIdx.x] = idx[(size_t)m * NKNN + threadIdx.x];
        sb[threadIdx.x] = bias[(size_t)m * NKNN + threadIdx.x];
    }
    __syncthreads();
    int hoff = warp * 64;
    float q0 = q[(size_t)m * CDIM + hoff + lane];
    float q1 = q[(size_t)m * CDIM + hoff + 32 + lane];
    float k0[NKNN], k1[NKNN];
#pragma unroll
    for (int kk = 0; kk < NKNN; kk++) {
        size_t base = ((size_t)b * NPTS + sj[kk]) * 512 + hoff;
        k0[kk] = kv[base + lane];
        k1[kk] = kv[base + 32 + lane];
    }
    float sc[NKNN];
#pragma unroll
    for (int kk = 0; kk < NKNN; kk++) {
        float d = q0 * k0[kk] + q1 * k1[kk];
#pragma unroll
        for (int o = 16; o > 0; o >>= 1) d += __shfl_xor_sync(0xffffffffu, d, o);
        sc[kk] = d * 0.125f + sb[kk];
    }
    float mx = -3.4e38f;
#pragma unroll
    for (int kk = 0; kk < NKNN; kk++) mx = fmaxf(mx, sc[kk]);
    float sum = 0.0f;
#pragma unroll
    for (int kk = 0; kk < NKNN; kk++) { sc[kk] = expf(sc[kk] - mx); sum += sc[kk]; }
    float inv = 1.0f / sum;
#pragma unroll
    for (int kk = 0; kk < NKNN; kk++) {
        size_t base = ((size_t)b * NPTS + sj[kk]) * 512 + 256 + hoff;
        k0[kk] = kv[base + lane];
        k1[kk] = kv[base + 32 + lane];
    }
    float o0 = 0.0f, o1 = 0.0f;
#pragma unroll
    for (int kk = 0; kk < NKNN; kk++) {
        float ww = sc[kk] * inv;
        o0 += ww * k0[kk];
        o1 += ww * k1[kk];
    }
    size_t ob = (size_t)m * CDIM + hoff;
    split1(o0, oh[ob + lane],      ol[ob + lane]);
    split1(o1, oh[ob + 32 + lane], ol[ob + 32 + lane]);
}

// ---------------- driver ----------------
extern "C" void kernel_launch(void* const* d_in, const int* in_sizes, int n_in,
                              void* d_out, int out_size) {
    const float* src1 = (const float*)d_in[0];
    const float* src2 = (const float*)d_in[1];
    const float* pos  = (const float*)d_in[2];
    const float* Wp   = (const float*)d_in[3];
    const float* bp   = (const float*)d_in[4];
    const float* Wr1  = (const float*)d_in[5];
    const float* br1  = (const float*)d_in[6];
    const float* Wr2  = (const float*)d_in[7];
    const float* br2  = (const float*)d_in[8];
    const float* Wqkv = (const float*)d_in[9];
    const float* bqkv = (const float*)d_in[10];
    const float* Wo   = (const float*)d_in[11];
    const float* bo   = (const float*)d_in[12];
    const float* g13  = (const float*)d_in[13];
    const float* b13  = (const float*)d_in[14];
    const float* g12  = (const float*)d_in[15];
    const float* b12  = (const float*)d_in[16];
    const float* W1   = (const float*)d_in[17];
    const float* b1   = (const float*)d_in[18];
    const float* W2   = (const float*)d_in[19];
    const float* b2   = (const float*)d_in[20];
    float* out = (float*)d_out;

    ushort_t *th, *tl, *xh, *xl, *aoh, *aol, *yh, *yl, *hh, *hl, *wh, *wl;
    float *x, *qb, *kvb, *tp, *bv;
    int* idxb;
    cudaGetSymbolAddress((void**)&th,  g_th);
    cudaGetSymbolAddress((void**)&tl,  g_tl);
    cudaGetSymbolAddress((void**)&x,   g_x);
    cudaGetSymbolAddress((void**)&xh,  g_xh);
    cudaGetSymbolAddress((void**)&xl,  g_xl);
    cudaGetSymbolAddress((void**)&qb,  g_q);
    cudaGetSymbolAddress((void**)&kvb, g_kv);
    cudaGetSymbolAddress((void**)&aoh, g_aoh);
    cudaGetSymbolAddress((void**)&aol, g_aol);
    cudaGetSymbolAddress((void**)&tp,  g_tp);
    cudaGetSymbolAddress((void**)&yh,  g_yh);
    cudaGetSymbolAddress((void**)&yl,  g_yl);
    cudaGetSymbolAddress((void**)&hh,  g_hh);
    cudaGetSymbolAddress((void**)&hl,  g_hl);
    cudaGetSymbolAddress((void**)&wh,  g_wh);
    cudaGetSymbolAddress((void**)&wl,  g_wl);
    cudaGetSymbolAddress((void**)&bv,  g_bv);
    cudaGetSymbolAddress((void**)&idxb, g_idx);

    split_weights<<<W_TOT / 256, 256>>>(Wp, Wqkv, Wo, W1, W2, wh, wl);

    dim3 gT(NPTS / 32, CDIM / 32, 8), bT(32, 8);
    transpose_kernel<<<gT, bT>>>(src1, src2, th, tl);

    // input proj (M = 16384) -> fp32 x
    mma_gemm<0><<<dim3(CDIM / 64, 2 * MTOK / 64), 128>>>(
        th, tl, wh + W_P, wl + W_P, bp, nullptr, nullptr, x, nullptr, nullptr, 2 * MTOK, CDIM, CDIM);

    // norm13 over both halves -> split
    ln2_kernel<<<2 * MTOK / 8, 256>>>(x, nullptr, nullptr, nullptr, g13, b13, xh, xl);

    knn_kernel<<<MTOK, 256>>>(pos, Wr1, br1, Wr2, br2, idxb, bv);

    // Q (fp32) and K|V (fp32, N=512)
    mma_gemm<0><<<dim3(CDIM / 64, MTOK / 64), 128>>>(
        xh, xl, wh + W_QKV, wl + W_QKV, bqkv, nullptr, nullptr, qb, nullptr, nullptr, MTOK, CDIM, CDIM);
    mma_gemm<0><<<dim3(512 / 64, MTOK / 64), 128>>>(
        xh + (size_t)MTOK * CDIM, xl + (size_t)MTOK * CDIM,
        wh + W_QKV + CDIM * CDIM, wl + W_QKV + CDIM * CDIM,
        bqkv + CDIM, nullptr, nullptr, kvb, nullptr, nullptr, MTOK, 512, CDIM);

    attn_kernel<<<MTOK, 128>>>(qb, kvb, idxb, bv, aoh, aol);

    // out-proj -> fp32 tp
    mma_gemm<0><<<dim3(CDIM / 64, MTOK / 64), 128>>>(
        aoh, aol, wh + W_O, wl + W_O, bo, nullptr, nullptr, tp, nullptr, nullptr, MTOK, CDIM, CDIM);

    // norm12: x1 (split) + tp -> y split
    ln2_kernel<<<MTOK / 8, 256>>>(nullptr, xh, xl, tp, g12, b12, yh, yl);

    // FFN
    mma_gemm<1><<<dim3(DFFN / 64, MTOK / 64), 128>>>(
        yh, yl, wh + W_1, wl + W_1, b1, nullptr, nullptr, nullptr, hh, hl, MTOK, DFFN, CDIM);
    mma_gemm<2><<<dim3(CDIM / 64, MTOK / 64), 128>>>(
        hh, hl, wh + W_2, wl + W_2, b2, yh, yl, out, nullptr, nullptr, MTOK, CDIM, DFFN);
}

// round 10
// speedup vs baseline: 1.5685x; 1.5685x over previous
#include <cuda_runtime.h>
#include <cuda_bf16.h>
#include <math.h>

#define NB    4
#define NPTS  2048
#define CDIM  256
#define DFFN  1024
#define NHEAD 4
#define NKNN  16
#define MTOK  (NB*NPTS)   // 8192

typedef unsigned short ushort_t;

// weight-split segment offsets (elements)
#define W_P    0
#define W_QKV  65536
#define W_O    262144
#define W_1    327680
#define W_2    589824
#define W_TOT  851968

// ---------------- scratch ----------------
__device__ __align__(16) float g_t [2*MTOK*CDIM];
__device__ __align__(16) float g_x [2*MTOK*CDIM];
__device__ __align__(16) float g_q [MTOK*CDIM];
__device__ __align__(16) float g_kv[MTOK*512];
__device__ __align__(16) float g_ao[MTOK*CDIM];
__device__ __align__(16) float g_tp[MTOK*CDIM];
__device__ __align__(16) float g_y [MTOK*CDIM];
__device__ __align__(16) float g_h [MTOK*DFFN];
__device__ __align__(16) ushort_t g_wh[W_TOT];
__device__ __align__(16) ushort_t g_wl[W_TOT];
__device__ __align__(16) int   g_idx[MTOK*NKNN];
__device__ __align__(16) float g_bv [MTOK*NKNN];

__device__ __forceinline__ float gelu_exact(float x) {
    return 0.5f * x * (1.0f + erff(x * 0.70710678118654752440f));
}

#define CP_ASYNC16(smem_u32, gptr) \
    asm volatile("cp.async.cg.shared.global [%0], [%1], 16;" :: "r"(smem_u32), "l"(gptr))

// split a float pair (x0 = even-k, x1 = odd-k) into packed bf16 hi and lo
__device__ __forceinline__ void split_pair(float x0, float x1, unsigned& hi, unsigned& lo) {
    unsigned r0 = __float_as_uint(x0), r1 = __float_as_uint(x1);
    asm("prmt.b32 %0, %1, %2, 0x7632;" : "=r"(hi) : "r"(r0), "r"(r1));
    float l0 = x0 - __uint_as_float(r0 & 0xffff0000u);
    float l1 = x1 - __uint_as_float(r1 & 0xffff0000u);
    asm("cvt.rn.bf16x2.f32 %0, %1, %2;" : "=r"(lo) : "f"(l1), "f"(l0));
}

// ---------------- weight split prep ----------------
__global__ void split_weights(const float* __restrict__ Wp, const float* __restrict__ Wqkv,
                              const float* __restrict__ Wo, const float* __restrict__ W1,
                              const float* __restrict__ W2,
                              ushort_t* __restrict__ wh, ushort_t* __restrict__ wl) {
    int i = blockIdx.x * 256 + threadIdx.x;
    if (i >= W_TOT) return;
    const float* src; int off;
    if      (i < W_QKV) { src = Wp;   off = i; }
    else if (i < W_O)   { src = Wqkv; off = i - W_QKV; }
    else if (i < W_1)   { src = Wo;   off = i - W_O; }
    else if (i < W_2)   { src = W1;   off = i - W_1; }
    else                { src = W2;   off = i - W_2; }
    float x = src[off];
    unsigned r = __float_as_uint(x);
    wh[i] = (ushort_t)(r >> 16);
    float lo = x - __uint_as_float(r & 0xffff0000u);
    __nv_bfloat16 lb = __float2bfloat16(lo);
    wl[i] = *reinterpret_cast<unsigned short*>(&lb);
}

// ---------------- fused transpose (B,C,N) -> (B,N,C) for src1|src2 ----------------
__global__ void transpose_kernel(const float* __restrict__ src1, const float* __restrict__ src2,
                                 float* __restrict__ out) {
    __shared__ float t[32][33];
    int z = blockIdx.z;
    const float* in = (z < 4) ? src1 : src2;
    int b = z & 3;
    float* dst = out + (size_t)(z < 4 ? 0 : MTOK * CDIM) + (size_t)b * NPTS * CDIM;
    const float* sp = in + (size_t)b * CDIM * NPTS;
    int n0 = blockIdx.x * 32, c0 = blockIdx.y * 32;
    int tx = threadIdx.x, ty = threadIdx.y;
#pragma unroll
    for (int i = 0; i < 4; i++)
        t[ty + 8 * i][tx] = sp[(size_t)(c0 + ty + 8 * i) * NPTS + n0 + tx];
    __syncthreads();
#pragma unroll
    for (int i = 0; i < 4; i++)
        dst[(size_t)(n0 + ty + 8 * i) * CDIM + c0 + tx] = t[tx][ty + 8 * i];
}

// ---------------- shared-memory overlays ----------------
#define SA  20
#define SBW 12
struct GemmSmem {
    float    As[2][64 * SA];    // 10240 B
    unsigned Bh[2][64 * SBW];   // 6144 B
    unsigned Bl[2][64 * SBW];   // 6144 B
};
#define TIECAP 128
struct KnnSmem {
    unsigned long long keys[NPTS];  // 16384 B
    int hist[256];
    int sel[NKNN];
    int tiebuf[TIECAP];
    int cnts[2];
    unsigned sh_prefix;
    int sh_krem;
};
#define FUSED_SMEM (sizeof(GemmSmem) > sizeof(KnnSmem) ? sizeof(GemmSmem) : sizeof(KnnSmem))

// ---------------- bf16x3 tensor-core GEMM body (proven R8 version) ----------------
// out[m,n] = epi( sum_k A[m,k]*W[n,k] + bias[n] ), W pre-split into bf16 hi/lo.
// CTA 64x64x16, 128 thr, warp tile 16m x 64n; mma.m16n8k16.bf16 x3 terms.
// MODE 0: plain   MODE 1: gelu   MODE 2: + res[m,n] fp32, store transposed (b,c,n)
template <int MODE>
__device__ __forceinline__ void gemm_body(GemmSmem* sm, int bx, int by,
        const float* __restrict__ A,
        const ushort_t* __restrict__ Wh, const ushort_t* __restrict__ Wl,
        const float* __restrict__ bias, const float* __restrict__ res,
        float* __restrict__ out, int M, int N, int K) {
    const int tid = threadIdx.x;
    const int lane = tid & 31, warp = tid >> 5;
    const int g = lane >> 2, tig = lane & 3;
    const int m0 = by * 64, n0 = bx * 64;

    const int lrow = tid >> 1, lh = tid & 1;
    const float* Ag = A + (size_t)(m0 + lrow) * K + lh * 8;
    const ushort_t* Whg = Wh + (size_t)(n0 + lrow) * K + lh * 8;
    const ushort_t* Wlg = Wl + (size_t)(n0 + lrow) * K + lh * 8;
    const unsigned sA  = (unsigned)__cvta_generic_to_shared(&sm->As[0][0]) + (unsigned)(lrow * SA + lh * 8) * 4;
    const unsigned sBh = (unsigned)__cvta_generic_to_shared(&sm->Bh[0][0]) + (unsigned)(lrow * 48 + lh * 16);
    const unsigned sBl = (unsigned)__cvta_generic_to_shared(&sm->Bl[0][0]) + (unsigned)(lrow * 48 + lh * 16);
    const unsigned ABUF = 64 * SA * 4, BBUF = 64 * SBW * 4;

    float c[8][4];
#pragma unroll
    for (int i = 0; i < 8; i++)
#pragma unroll
        for (int j = 0; j < 4; j++) c[i][j] = 0.0f;

    const int nIter = K / 16;
    {
        CP_ASYNC16(sA, Ag);
        CP_ASYNC16(sA + 16, Ag + 4);
        CP_ASYNC16(sBh, Whg);
        CP_ASYNC16(sBl, Wlg);
        asm volatile("cp.async.commit_group;");
    }

    const int arow = warp * 16 + g;
    for (int kt = 0; kt < nIter; kt++) {
        asm volatile("cp.async.wait_group 0;");
        __syncthreads();
        const int buf = kt & 1;
        if (kt + 1 < nIter) {
            const int k1 = (kt + 1) * 16;
            const unsigned db = (buf ^ 1);
            CP_ASYNC16(sA + db * ABUF, Ag + k1);
            CP_ASYNC16(sA + db * ABUF + 16, Ag + k1 + 4);
            CP_ASYNC16(sBh + db * BBUF, Whg + k1);
            CP_ASYNC16(sBl + db * BBUF, Wlg + k1);
            asm volatile("cp.async.commit_group;");
        }
        const float*    as = &sm->As[buf][0];
        const unsigned* bh = &sm->Bh[buf][0];
        const unsigned* bl = &sm->Bl[buf][0];

        unsigned AH[4], AL[4];
#pragma unroll
        for (int p = 0; p < 2; p++)
#pragma unroll
            for (int r = 0; r < 2; r++) {
                const float* ap = as + (arow + r * 8) * SA + p * 8 + 2 * tig;
                float2 xv = *reinterpret_cast<const float2*>(ap);
                split_pair(xv.x, xv.y, AH[p * 2 + r], AL[p * 2 + r]);
            }
#pragma unroll
        for (int nt = 0; nt < 8; nt++) {
            const int bn = nt * 8 + g;
            unsigned bh0 = bh[bn * SBW + tig],     bh1 = bh[bn * SBW + 4 + tig];
            unsigned bl0 = bl[bn * SBW + tig],     bl1 = bl[bn * SBW + 4 + tig];
            float* cc = c[nt];
#define MMA_BF16(A0,A1,A2,A3,B0,B1) \
    asm volatile("mma.sync.aligned.m16n8k16.row.col.f32.bf16.bf16.f32 " \
        "{%0,%1,%2,%3}, {%4,%5,%6,%7}, {%8,%9}, {%0,%1,%2,%3};" \
        : "+f"(cc[0]), "+f"(cc[1]), "+f"(cc[2]), "+f"(cc[3]) \
        : "r"(A0), "r"(A1), "r"(A2), "r"(A3), "r"(B0), "r"(B1))
            MMA_BF16(AH[0], AH[1], AH[2], AH[3], bl0, bl1);
            MMA_BF16(AL[0], AL[1], AL[2], AL[3], bh0, bh1);
            MMA_BF16(AH[0], AH[1], AH[2], AH[3], bh0, bh1);
#undef MMA_BF16
        }
        __syncthreads();
    }

#pragma unroll
    for (int nt = 0; nt < 8; nt++) {
        int col = n0 + nt * 8 + tig * 2;
        float b0 = bias[col], b1 = bias[col + 1];
#pragma unroll
        for (int half = 0; half < 2; half++) {
            int m = m0 + warp * 16 + g + half * 8;
            float v0 = c[nt][half * 2 + 0] + b0;
            float v1 = c[nt][half * 2 + 1] + b1;
            if (MODE == 1) { v0 = gelu_exact(v0); v1 = gelu_exact(v1); }
            if (MODE == 2) {
                v0 += res[(size_t)m * CDIM + col];
                v1 += res[(size_t)m * CDIM + col + 1];
                int b = m >> 11, nn = m & (NPTS - 1);
                out[((size_t)b * CDIM + col) * NPTS + nn]     = v0;
                out[((size_t)b * CDIM + col + 1) * NPTS + nn] = v1;
            } else {
                *reinterpret_cast<float2*>(out + (size_t)m * N + col) = make_float2(v0, v1);
            }
        }
    }
}

template <int MODE>
__global__ void __launch_bounds__(128) mma_gemm(
        const float* __restrict__ A,
        const ushort_t* __restrict__ Wh, const ushort_t* __restrict__ Wl,
        const float* __restrict__ bias, const float* __restrict__ res,
        float* __restrict__ out, int M, int N, int K) {
    __shared__ GemmSmem sm;
    gemm_body<MODE>(&sm, blockIdx.x, blockIdx.y, A, Wh, Wl, bias, res, out, M, N, K);
}

// ---------------- KNN top-16 via exact 4-round radix select + bias MLP (128 threads) ------
__device__ __forceinline__ void knn_body(KnnSmem* sm, int bq,
        const float* __restrict__ pos,
        const float* __restrict__ Wr1, const float* __restrict__ br1,
        const float* __restrict__ Wr2, const float* __restrict__ br2,
        int* __restrict__ idx_out, float* __restrict__ bias_out) {
    int b = bq >> 11, i = bq & (NPTS - 1);
    int t = threadIdx.x;          // 0..127
    const float* P = pos + (size_t)b * 3 * NPTS;
    float xi = P[i], yi = P[NPTS + i], zi = P[2 * NPTS + i];
    float sqi = xi * xi + yi * yi + zi * zi;
    for (int j = t; j < NPTS; j += 128) {
        float xj = P[j], yj = P[NPTS + j], zj = P[2 * NPTS + j];
        float sqj = xj * xj + yj * yj + zj * zj;
        float dot = xi * xj + yi * yj + zi * zj;
        float dist = sqi + sqj - 2.0f * dot;
        unsigned db = __float_as_uint(dist);
        db = (db & 0x80000000u) ? ~db : (db | 0x80000000u);
        sm->keys[j] = ((unsigned long long)db << 32) | (unsigned)j;
    }
    if (t == 0) { sm->cnts[0] = 0; sm->cnts[1] = 0; }

    unsigned prefix = 0;
    int krem = NKNN;
#pragma unroll
    for (int r = 0; r < 4; r++) {
        const int shift = 24 - 8 * r;
        sm->hist[t] = 0;
        sm->hist[t + 128] = 0;
        __syncthreads();
        for (int j = t; j < NPTS; j += 128) {
            unsigned d32 = (unsigned)(sm->keys[j] >> 32);
            bool match = (r == 0) || ((d32 >> (shift + 8)) == (prefix >> (shift + 8)));
            if (match) {
                int digit = (d32 >> shift) & 0xFF;
                unsigned mask = __match_any_sync(__activemask(), digit);
                int leader = __ffs(mask) - 1;
                if ((int)(t & 31) == leader) atomicAdd(&sm->hist[digit], __popc(mask));
            }
        }
        __syncthreads();
        if (t < 32) {
            int loc[8], s = 0;
#pragma unroll
            for (int u = 0; u < 8; u++) { loc[u] = s; s += sm->hist[t * 8 + u]; }
            int run = s;
#pragma unroll
            for (int o = 1; o < 32; o <<= 1) {
                int v = __shfl_up_sync(0xffffffffu, run, o);
                if (t >= o) run += v;
            }
            int excl = run - s;
#pragma unroll
            for (int u = 0; u < 8; u++) {
                int below = excl + loc[u];
                int c = sm->hist[t * 8 + u];
                if (below < krem && krem <= below + c) {
                    sm->sh_prefix = prefix | ((unsigned)(t * 8 + u) << shift);
                    sm->sh_krem = krem - below;
                }
            }
        }
        __syncthreads();
        prefix = sm->sh_prefix;
        krem = sm->sh_krem;
        __syncthreads();
    }

    for (int j = t; j < NPTS; j += 128) {
        unsigned d32 = (unsigned)(sm->keys[j] >> 32);
        if (d32 < prefix) {
            int p = atomicAdd(&sm->cnts[0], 1);
            sm->sel[p] = j;
        } else if (d32 == prefix) {
            int p = atomicAdd(&sm->cnts[1], 1);
            if (p < TIECAP) sm->tiebuf[p] = j;
        }
    }
    __syncthreads();
    if (t == 0) {
        int na = sm->cnts[0];
        int nt = sm->cnts[1] < TIECAP ? sm->cnts[1] : TIECAP;
        for (int a = 1; a < na; a++) {
            int v = sm->sel[a], p = a - 1;
            while (p >= 0 && sm->sel[p] > v) { sm->sel[p + 1] = sm->sel[p]; p--; }
            sm->sel[p + 1] = v;
        }
        for (int s = 0; s < NKNN - na; s++) {
            int bestv = 1 << 30, bi = 0;
            for (int u = 0; u < nt; u++)
                if (sm->tiebuf[u] < bestv) { bestv = sm->tiebuf[u]; bi = u; }
            sm->sel[na + s] = bestv;
            sm->tiebuf[bi] = 1 << 30;
        }
    }
    __syncthreads();

    if (t < NKNN) {
        int j = sm->sel[t];
        float rx = xi - P[j], ry = yi - P[NPTS + j], rz = zi - P[2 * NPTS + j];
        float acc = 0.0f;
#pragma unroll 8
        for (int o = 0; o < 64; o++) {
            float hp = Wr1[o * 3] * rx + Wr1[o * 3 + 1] * ry + Wr1[o * 3 + 2] * rz + br1[o];
            acc += Wr2[o] * gelu_exact(hp);
        }
        idx_out[(size_t)bq * NKNN + t] = j;
        bias_out[(size_t)bq * NKNN + t] = acc + br2[0];
    }
}

// ---------------- fused proj-GEMM + KNN launch ----------------
// blocks [0, 1024): proj GEMM tiles (bx = id & 3, by = id >> 2), M = 2*MTOK, N = CDIM, K = CDIM
// blocks [1024, 1024 + MTOK): KNN query blocks
__global__ void __launch_bounds__(128) proj_knn_kernel(
        const float* __restrict__ A,
        const ushort_t* __restrict__ Wh, const ushort_t* __restrict__ Wl,
        const float* __restrict__ bias, float* __restrict__ out,
        const float* __restrict__ pos,
        const float* __restrict__ Wr1, const float* __restrict__ br1,
        const float* __restrict__ Wr2, const float* __restrict__ br2,
        int* __restrict__ idx_out, float* __restrict__ bias_out) {
    __shared__ __align__(16) char smraw[FUSED_SMEM];
    int bid = blockIdx.x;
    if (bid < 1024) {
        gemm_body<0>(reinterpret_cast<GemmSmem*>(smraw), bid & 3, bid >> 2,
                     A, Wh, Wl, bias, nullptr, out, 2 * MTOK, CDIM, CDIM);
    } else {
        knn_body(reinterpret_cast<KnnSmem*>(smraw), bid - 1024,
                 pos, Wr1, br1, Wr2, br2, idx_out, bias_out);
    }
}

// ---------------- LayerNorm: warp per row (256 cols), optional residual ----------------
__global__ void ln2_kernel(const float* __restrict__ x, const float* __restrict__ res,
                           const float* __restrict__ g, const float* __restrict__ be,
                           float* __restrict__ out) {
    int warp = threadIdx.x >> 5, lane = threadIdx.x & 31;
    size_t row = (size_t)blockIdx.x * 8 + warp;
    const float* xr = x + row * CDIM;
    float v[8], s = 0.0f, s2 = 0.0f;
#pragma unroll
    for (int i = 0; i < 8; i++) {
        v[i] = xr[i * 32 + lane];
        if (res) v[i] += res[row * CDIM + i * 32 + lane];
        s += v[i]; s2 += v[i] * v[i];
    }
#pragma unroll
    for (int o = 16; o > 0; o >>= 1) {
        s  += __shfl_xor_sync(0xffffffffu, s, o);
        s2 += __shfl_xor_sync(0xffffffffu, s2, o);
    }
    float mean = s * (1.0f / 256.0f);
    float var  = s2 * (1.0f / 256.0f) - mean * mean;
    float rstd = rsqrtf(var + 1e-5f);
#pragma unroll
    for (int i = 0; i < 8; i++)
        out[row * CDIM + i * 32 + lane] = (v[i] - mean) * rstd * g[i * 32 + lane] + be[i * 32 + lane];
}

// ---------------- sparse attention (kv packed: row = [k(256) | v(256)]) ----------------
__global__ void attn_kernel(const float* __restrict__ q, const float* __restrict__ kv,
                            const int* __restrict__ idx, const float* __restrict__ bias,
                            float* __restrict__ out) {
    __shared__ int   sj[NKNN];
    __shared__ float sb[NKNN];
    int m = blockIdx.x;
    int b = m >> 11;
    int warp = threadIdx.x >> 5, lane = threadIdx.x & 31;
    if (threadIdx.x < NKNN) {
        sj[threadIdx.x] = idx[(size_t)m * NKNN + threadIdx.x];
        sb[threadIdx.x] = bias[(size_t)m * NKNN + threadIdx.x];
    }
    __syncthreads();
    int hoff = warp * 64;
    float q0 = q[(size_t)m * CDIM + hoff + lane];
    float q1 = q[(size_t)m * CDIM + hoff + 32 + lane];
    float k0[NKNN], k1[NKNN];
#pragma unroll
    for (int kk = 0; kk < NKNN; kk++) {
        size_t base = ((size_t)b * NPTS + sj[kk]) * 512 + hoff;
        k0[kk] = kv[base + lane];
        k1[kk] = kv[base + 32 + lane];
    }
    float sc[NKNN];
#pragma unroll
    for (int kk = 0; kk < NKNN; kk++) {
        float d = q0 * k0[kk] + q1 * k1[kk];
#pragma unroll
        for (int o = 16; o > 0; o >>= 1) d += __shfl_xor_sync(0xffffffffu, d, o);
        sc[kk] = d * 0.125f + sb[kk];
    }
    float mx = -3.4e38f;
#pragma unroll
    for (int kk = 0; kk < NKNN; kk++) mx = fmaxf(mx, sc[kk]);
    float sum = 0.0f;
#pragma unroll
    for (int kk = 0; kk < NKNN; kk++) { sc[kk] = expf(sc[kk] - mx); sum += sc[kk]; }
    float inv = 1.0f / sum;
#pragma unroll
    for (int kk = 0; kk < NKNN; kk++) {
        size_t base = ((size_t)b * NPTS + sj[kk]) * 512 + 256 + hoff;
        k0[kk] = kv[base + lane];
        k1[kk] = kv[base + 32 + lane];
    }
    float o0 = 0.0f, o1 = 0.0f;
#pragma unroll
    for (int kk = 0; kk < NKNN; kk++) {
        float ww = sc[kk] * inv;
        o0 += ww * k0[kk];
        o1 += ww * k1[kk];
    }
    out[(size_t)m * CDIM + hoff + lane]      = o0;
    out[(size_t)m * CDIM + hoff + 32 + lane] = o1;
}

// ---------------- driver ----------------
extern "C" void kernel_launch(void* const* d_in, const int* in_sizes, int n_in,
                              void* d_out, int out_size) {
    const float* src1 = (const float*)d_in[0];
    const float* src2 = (const float*)d_in[1];
    const float* pos  = (const float*)d_in[2];
    const float* Wp   = (const float*)d_in[3];
    const float* bp   = (const float*)d_in[4];
    const float* Wr1  = (const float*)d_in[5];
    const float* br1  = (const float*)d_in[6];
    const float* Wr2  = (const float*)d_in[7];
    const float* br2  = (const float*)d_in[8];
    const float* Wqkv = (const float*)d_in[9];
    const float* bqkv = (const float*)d_in[10];
    const float* Wo   = (const float*)d_in[11];
    const float* bo   = (const float*)d_in[12];
    const float* g13  = (const float*)d_in[13];
    const float* b13  = (const float*)d_in[14];
    const float* g12  = (const float*)d_in[15];
    const float* b12  = (const float*)d_in[16];
    const float* W1   = (const float*)d_in[17];
    const float* b1   = (const float*)d_in[18];
    const float* W2   = (const float*)d_in[19];
    const float* b2   = (const float*)d_in[20];
    float* out = (float*)d_out;

    float *t, *x, *qb, *kvb, *ao, *tp, *y, *h, *bv;
    ushort_t *wh, *wl;
    int* idxb;
    cudaGetSymbolAddress((void**)&t,  g_t);
    cudaGetSymbolAddress((void**)&x,  g_x);
    cudaGetSymbolAddress((void**)&qb, g_q);
    cudaGetSymbolAddress((void**)&kvb, g_kv);
    cudaGetSymbolAddress((void**)&ao, g_ao);
    cudaGetSymbolAddress((void**)&tp, g_tp);
    cudaGetSymbolAddress((void**)&y,  g_y);
    cudaGetSymbolAddress((void**)&h,  g_h);
    cudaGetSymbolAddress((void**)&wh, g_wh);
    cudaGetSymbolAddress((void**)&wl, g_wl);
    cudaGetSymbolAddress((void**)&bv, g_bv);
    cudaGetSymbolAddress((void**)&idxb, g_idx);

    split_weights<<<(W_TOT + 255) / 256, 256>>>(Wp, Wqkv, Wo, W1, W2, wh, wl);

    dim3 gT(NPTS / 32, CDIM / 32, 8), bT(32, 8);
    transpose_kernel<<<gT, bT>>>(src1, src2, t);

    // fused: input proj (both streams, M = 16384) + KNN/bias (independent work)
    proj_knn_kernel<<<1024 + MTOK, 128>>>(t, wh + W_P, wl + W_P, bp, x,
                                          pos, Wr1, br1, Wr2, br2, idxb, bv);

    ln2_kernel<<<2 * MTOK / 8, 256>>>(x, nullptr, g13, b13, x);

    mma_gemm<0><<<dim3(CDIM / 64, MTOK / 64), 128>>>(x, wh + W_QKV, wl + W_QKV, bqkv, nullptr, qb, MTOK, CDIM, CDIM);
    mma_gemm<0><<<dim3(512 / 64, MTOK / 64), 128>>>(x + (size_t)MTOK * CDIM,
                                                    wh + W_QKV + CDIM * CDIM, wl + W_QKV + CDIM * CDIM,
                                                    bqkv + CDIM, nullptr, kvb, MTOK, 512, CDIM);

    attn_kernel<<<MTOK, 128>>>(qb, kvb, idxb, bv, ao);

    mma_gemm<0><<<dim3(CDIM / 64, MTOK / 64), 128>>>(ao, wh + W_O, wl + W_O, bo, nullptr, tp, MTOK, CDIM, CDIM);

    ln2_kernel<<<MTOK / 8, 256>>>(x, tp, g12, b12, y);

    mma_gemm<1><<<dim3(DFFN / 64, MTOK / 64), 128>>>(y, wh + W_1, wl + W_1, b1, nullptr, h, MTOK, DFFN, CDIM);
    mma_gemm<2><<<dim3(CDIM / 64, MTOK / 64), 128>>>(h, wh + W_2, wl + W_2, b2, y, out, MTOK, CDIM, DFFN);
}

// round 12
// speedup vs baseline: 1.6787x; 1.0703x over previous
#include <cuda_runtime.h>
#include <cuda_bf16.h>
#include <math.h>

#define NB    4
#define NPTS  2048
#define CDIM  256
#define DFFN  1024
#define NHEAD 4
#define NKNN  16
#define MTOK  (NB*NPTS)   // 8192

typedef unsigned short ushort_t;

// weight-split segment offsets (elements)
#define W_P    0
#define W_QKV  65536
#define W_O    262144
#define W_1    327680
#define W_2    589824
#define W_TOT  851968

// ---------------- scratch ----------------
__device__ __align__(16) float g_t [2*MTOK*CDIM];
__device__ __align__(16) float g_x [2*MTOK*CDIM];
__device__ __align__(16) float g_q [MTOK*CDIM];
__device__ __align__(16) float g_kv[MTOK*512];
__device__ __align__(16) float g_ao[MTOK*CDIM];
__device__ __align__(16) float g_tp[MTOK*CDIM];
__device__ __align__(16) float g_y [MTOK*CDIM];
__device__ __align__(16) float g_h [MTOK*DFFN];
__device__ __align__(16) ushort_t g_wh[W_TOT];
__device__ __align__(16) ushort_t g_wl[W_TOT];
__device__ __align__(16) int   g_idx[MTOK*NKNN];
__device__ __align__(16) float g_bv [MTOK*NKNN];

__device__ __forceinline__ float gelu_exact(float x) {
    return 0.5f * x * (1.0f + erff(x * 0.70710678118654752440f));
}

#define CP_ASYNC16(smem_u32, gptr) \
    asm volatile("cp.async.cg.shared.global [%0], [%1], 16;" :: "r"(smem_u32), "l"(gptr))

#define LDSM4(R, addr) \
    asm volatile("ldmatrix.sync.aligned.m8n8.x4.shared.b16 {%0,%1,%2,%3}, [%4];" \
        : "=r"((R)[0]), "=r"((R)[1]), "=r"((R)[2]), "=r"((R)[3]) : "r"(addr))

// split a float pair (x0 = even-k, x1 = odd-k) into packed bf16 hi and lo
__device__ __forceinline__ void split_pair(float x0, float x1, unsigned& hi, unsigned& lo) {
    unsigned r0 = __float_as_uint(x0), r1 = __float_as_uint(x1);
    asm("prmt.b32 %0, %1, %2, 0x7632;" : "=r"(hi) : "r"(r0), "r"(r1));
    float l0 = x0 - __uint_as_float(r0 & 0xffff0000u);
    float l1 = x1 - __uint_as_float(r1 & 0xffff0000u);
    asm("cvt.rn.bf16x2.f32 %0, %1, %2;" : "=r"(lo) : "f"(l1), "f"(l0));
}

// ---------------- fused prep: transpose (4096 blocks) + weight split (3328 blocks) ------
__global__ void __launch_bounds__(256) prep_kernel(
        const float* __restrict__ src1, const float* __restrict__ src2,
        float* __restrict__ tout,
        const float* __restrict__ Wp, const float* __restrict__ Wqkv,
        const float* __restrict__ Wo, const float* __restrict__ W1,
        const float* __restrict__ W2,
        ushort_t* __restrict__ wh, ushort_t* __restrict__ wl) {
    int bid = blockIdx.x;
    if (bid < 4096) {
        __shared__ float t[32][33];
        int n0 = (bid & 63) * 32, c0 = ((bid >> 6) & 7) * 32, z = bid >> 9;
        const float* in = (z < 4) ? src1 : src2;
        int b = z & 3;
        float* dst = tout + (size_t)(z < 4 ? 0 : MTOK * CDIM) + (size_t)b * NPTS * CDIM;
        const float* sp = in + (size_t)b * CDIM * NPTS;
        int tx = threadIdx.x & 31, ty = threadIdx.x >> 5;
#pragma unroll
        for (int i = 0; i < 4; i++)
            t[ty + 8 * i][tx] = sp[(size_t)(c0 + ty + 8 * i) * NPTS + n0 + tx];
        __syncthreads();
#pragma unroll
        for (int i = 0; i < 4; i++)
            dst[(size_t)(n0 + ty + 8 * i) * CDIM + c0 + tx] = t[tx][ty + 8 * i];
    } else {
        int i = (bid - 4096) * 256 + threadIdx.x;
        if (i >= W_TOT) return;
        const float* src; int off;
        if      (i < W_QKV) { src = Wp;   off = i; }
        else if (i < W_O)   { src = Wqkv; off = i - W_QKV; }
        else if (i < W_1)   { src = Wo;   off = i - W_O; }
        else if (i < W_2)   { src = W1;   off = i - W_1; }
        else                { src = W2;   off = i - W_2; }
        float x = src[off];
        unsigned r = __float_as_uint(x);
        wh[i] = (ushort_t)(r >> 16);
        float lo = x - __uint_as_float(r & 0xffff0000u);
        __nv_bfloat16 lb = __float2bfloat16(lo);
        wl[i] = *reinterpret_cast<unsigned short*>(&lb);
    }
}

// ---------------- shared-memory overlays ----------------
#define SA  20
#define SBW 12
struct GemmSmem {
    float    As[2][64 * SA];    // 10240 B
    unsigned Bh[2][64 * SBW];   // 6144 B
    unsigned Bl[2][64 * SBW];   // 6144 B
};
#define TIECAP 128
struct KnnSmem {
    unsigned long long keys[NPTS];  // 16384 B
    int hist[256];
    int sel[NKNN];
    int tiebuf[TIECAP];
    int cnts[2];
    unsigned sh_prefix;
    int sh_krem;
};
#define FUSED_SMEM (sizeof(GemmSmem) > sizeof(KnnSmem) ? sizeof(GemmSmem) : sizeof(KnnSmem))

// ---------------- bf16x3 tensor-core GEMM body ----------------
// out[m,n] = epi( sum_k A[m,k]*W[n,k] + bias[n] ), W pre-split into bf16 hi/lo.
// CTA 64x64x16, 128 thr, warp tile 16m x 64n; A: fp32 LDS + split; B: ldmatrix.x4.
// MODE 0: plain   MODE 1: gelu   MODE 2: + res[m,n] fp32, store transposed (b,c,n)
template <int MODE>
__device__ __forceinline__ void gemm_body(GemmSmem* sm, int bx, int by,
        const float* __restrict__ A,
        const ushort_t* __restrict__ Wh, const ushort_t* __restrict__ Wl,
        const float* __restrict__ bias, const float* __restrict__ res,
        float* __restrict__ out, int M, int N, int K) {
    const int tid = threadIdx.x;
    const int lane = tid & 31, warp = tid >> 5;
    const int g = lane >> 2, tig = lane & 3;
    const int m0 = by * 64, n0 = bx * 64;

    const int lrow = tid >> 1, lh = tid & 1;
    const float* Ag = A + (size_t)(m0 + lrow) * K + lh * 8;
    const ushort_t* Whg = Wh + (size_t)(n0 + lrow) * K + lh * 8;
    const ushort_t* Wlg = Wl + (size_t)(n0 + lrow) * K + lh * 8;
    const unsigned sA  = (unsigned)__cvta_generic_to_shared(&sm->As[0][0]) + (unsigned)(lrow * SA + lh * 8) * 4;
    const unsigned sBh = (unsigned)__cvta_generic_to_shared(&sm->Bh[0][0]) + (unsigned)(lrow * 48 + lh * 16);
    const unsigned sBl = (unsigned)__cvta_generic_to_shared(&sm->Bl[0][0]) + (unsigned)(lrow * 48 + lh * 16);
    const unsigned ABUF = 64 * SA * 4, BBUF = 64 * SBW * 4;

    // ldmatrix base addresses for B fragments: lane -> (n-row, k-half)
    const unsigned boff = (unsigned)(((lane & 7) + ((lane >> 4) & 1) * 8) * 48 + ((lane >> 3) & 1) * 16);
    const unsigned bhL = (unsigned)__cvta_generic_to_shared(&sm->Bh[0][0]) + boff;
    const unsigned blL = (unsigned)__cvta_generic_to_shared(&sm->Bl[0][0]) + boff;

    float c[8][4];
#pragma unroll
    for (int i = 0; i < 8; i++)
#pragma unroll
        for (int j = 0; j < 4; j++) c[i][j] = 0.0f;

    const int nIter = K / 16;
    {
        CP_ASYNC16(sA, Ag);
        CP_ASYNC16(sA + 16, Ag + 4);
        CP_ASYNC16(sBh, Whg);
        CP_ASYNC16(sBl, Wlg);
        asm volatile("cp.async.commit_group;");
    }

    const int arow = warp * 16 + g;
    for (int kt = 0; kt < nIter; kt++) {
        asm volatile("cp.async.wait_group 0;");
        __syncthreads();
        const int buf = kt & 1;
        if (kt + 1 < nIter) {
            const int k1 = (kt + 1) * 16;
            const unsigned db = (buf ^ 1);
            CP_ASYNC16(sA + db * ABUF, Ag + k1);
            CP_ASYNC16(sA + db * ABUF + 16, Ag + k1 + 4);
            CP_ASYNC16(sBh + db * BBUF, Whg + k1);
            CP_ASYNC16(sBl + db * BBUF, Wlg + k1);
            asm volatile("cp.async.commit_group;");
        }
        const float* as = &sm->As[buf][0];

        unsigned AH[4], AL[4];
#pragma unroll
        for (int p = 0; p < 2; p++)
#pragma unroll
            for (int r = 0; r < 2; r++) {
                const float* ap = as + (arow + r * 8) * SA + p * 8 + 2 * tig;
                float2 xv = *reinterpret_cast<const float2*>(ap);
                split_pair(xv.x, xv.y, AH[p * 2 + r], AL[p * 2 + r]);
            }
#pragma unroll
        for (int nt2 = 0; nt2 < 4; nt2++) {
            unsigned BH[4], BL[4];
            LDSM4(BH, bhL + buf * BBUF + nt2 * 16 * 48);
            LDSM4(BL, blL + buf * BBUF + nt2 * 16 * 48);
            float* c0 = c[2 * nt2];
            float* c1 = c[2 * nt2 + 1];
#define MMA_BF16(CC, A0,A1,A2,A3, B0,B1) \
    asm volatile("mma.sync.aligned.m16n8k16.row.col.f32.bf16.bf16.f32 " \
        "{%0,%1,%2,%3}, {%4,%5,%6,%7}, {%8,%9}, {%0,%1,%2,%3};" \
        : "+f"((CC)[0]), "+f"((CC)[1]), "+f"((CC)[2]), "+f"((CC)[3]) \
        : "r"(A0), "r"(A1), "r"(A2), "r"(A3), "r"(B0), "r"(B1))
            MMA_BF16(c0, AH[0],AH[1],AH[2],AH[3], BL[0],BL[1]);
            MMA_BF16(c0, AL[0],AL[1],AL[2],AL[3], BH[0],BH[1]);
            MMA_BF16(c0, AH[0],AH[1],AH[2],AH[3], BH[0],BH[1]);
            MMA_BF16(c1, AH[0],AH[1],AH[2],AH[3], BL[2],BL[3]);
            MMA_BF16(c1, AL[0],AL[1],AL[2],AL[3], BH[2],BH[3]);
            MMA_BF16(c1, AH[0],AH[1],AH[2],AH[3], BH[2],BH[3]);
#undef MMA_BF16
        }
        __syncthreads();
    }

#pragma unroll
    for (int nt = 0; nt < 8; nt++) {
        int col = n0 + nt * 8 + tig * 2;
        float b0 = bias[col], b1 = bias[col + 1];
#pragma unroll
        for (int half = 0; half < 2; half++) {
            int m = m0 + warp * 16 + g + half * 8;
            float v0 = c[nt][half * 2 + 0] + b0;
            float v1 = c[nt][half * 2 + 1] + b1;
            if (MODE == 1) { v0 = gelu_exact(v0); v1 = gelu_exact(v1); }
            if (MODE == 2) {
                v0 += res[(size_t)m * CDIM + col];
                v1 += res[(size_t)m * CDIM + col + 1];
                int b = m >> 11, nn = m & (NPTS - 1);
                out[((size_t)b * CDIM + col) * NPTS + nn]     = v0;
                out[((size_t)b * CDIM + col + 1) * NPTS + nn] = v1;
            } else {
                *reinterpret_cast<float2*>(out + (size_t)m * N + col) = make_float2(v0, v1);
            }
        }
    }
}

template <int MODE>
__global__ void __launch_bounds__(128) mma_gemm(
        const float* __restrict__ A,
        const ushort_t* __restrict__ Wh, const ushort_t* __restrict__ Wl,
        const float* __restrict__ bias, const float* __restrict__ res,
        float* __restrict__ out, int M, int N, int K) {
    __shared__ GemmSmem sm;
    gemm_body<MODE>(&sm, blockIdx.x, blockIdx.y, A, Wh, Wl, bias, res, out, M, N, K);
}

// ---------------- fused Q + KV GEMM launch ----------------
// blocks [0,512): Q (N=CDIM), blocks [512,1536): KV (N=512)
__global__ void __launch_bounds__(128) qkv_kernel(
        const float* __restrict__ x,
        const ushort_t* __restrict__ wh, const ushort_t* __restrict__ wl,
        const float* __restrict__ bqkv,
        float* __restrict__ qb, float* __restrict__ kvb) {
    __shared__ GemmSmem sm;
    int bid = blockIdx.x;
    if (bid < 512) {
        gemm_body<0>(&sm, bid & 3, bid >> 2, x, wh + W_QKV, wl + W_QKV, bqkv,
                     nullptr, qb, MTOK, CDIM, CDIM);
    } else {
        int b2 = bid - 512;
        gemm_body<0>(&sm, b2 & 7, b2 >> 3, x + (size_t)MTOK * CDIM,
                     wh + W_QKV + CDIM * CDIM, wl + W_QKV + CDIM * CDIM,
                     bqkv + CDIM, nullptr, kvb, MTOK, 512, CDIM);
    }
}

// ---------------- KNN top-16 via exact 4-round radix select + bias MLP (128 threads) ------
__device__ __forceinline__ void knn_body(KnnSmem* sm, int bq,
        const float* __restrict__ pos,
        const float* __restrict__ Wr1, const float* __restrict__ br1,
        const float* __restrict__ Wr2, const float* __restrict__ br2,
        int* __restrict__ idx_out, float* __restrict__ bias_out) {
    int b = bq >> 11, i = bq & (NPTS - 1);
    int t = threadIdx.x;          // 0..127
    const float* P = pos + (size_t)b * 3 * NPTS;
    float xi = P[i], yi = P[NPTS + i], zi = P[2 * NPTS + i];
    float sqi = xi * xi + yi * yi + zi * zi;
    for (int j = t; j < NPTS; j += 128) {
        float xj = P[j], yj = P[NPTS + j], zj = P[2 * NPTS + j];
        float sqj = xj * xj + yj * yj + zj * zj;
        float dot = xi * xj + yi * yj + zi * zj;
        float dist = sqi + sqj - 2.0f * dot;
        unsigned db = __float_as_uint(dist);
        db = (db & 0x80000000u) ? ~db : (db | 0x80000000u);
        sm->keys[j] = ((unsigned long long)db << 32) | (unsigned)j;
    }
    if (t == 0) { sm->cnts[0] = 0; sm->cnts[1] = 0; }

    unsigned prefix = 0;
    int krem = NKNN;
#pragma unroll
    for (int r = 0; r < 4; r++) {
        const int shift = 24 - 8 * r;
        sm->hist[t] = 0;
        sm->hist[t + 128] = 0;
        __syncthreads();
        for (int j = t; j < NPTS; j += 128) {
            unsigned d32 = (unsigned)(sm->keys[j] >> 32);
            bool match = (r == 0) || ((d32 >> (shift + 8)) == (prefix >> (shift + 8)));
            if (match) {
                int digit = (d32 >> shift) & 0xFF;
                unsigned mask = __match_any_sync(__activemask(), digit);
                int leader = __ffs(mask) - 1;
                if ((int)(t & 31) == leader) atomicAdd(&sm->hist[digit], __popc(mask));
            }
        }
        __syncthreads();
        if (t < 32) {
            int loc[8], s = 0;
#pragma unroll
            for (int u = 0; u < 8; u++) { loc[u] = s; s += sm->hist[t * 8 + u]; }
            int run = s;
#pragma unroll
            for (int o = 1; o < 32; o <<= 1) {
                int v = __shfl_up_sync(0xffffffffu, run, o);
                if (t >= o) run += v;
            }
            int excl = run - s;
#pragma unroll
            for (int u = 0; u < 8; u++) {
                int below = excl + loc[u];
                int c = sm->hist[t * 8 + u];
                if (below < krem && krem <= below + c) {
                    sm->sh_prefix = prefix | ((unsigned)(t * 8 + u) << shift);
                    sm->sh_krem = krem - below;
                }
            }
        }
        __syncthreads();
        prefix = sm->sh_prefix;
        krem = sm->sh_krem;
        __syncthreads();
    }

    for (int j = t; j < NPTS; j += 128) {
        unsigned d32 = (unsigned)(sm->keys[j] >> 32);
        if (d32 < prefix) {
            int p = atomicAdd(&sm->cnts[0], 1);
            sm->sel[p] = j;
        } else if (d32 == prefix) {
            int p = atomicAdd(&sm->cnts[1], 1);
            if (p < TIECAP) sm->tiebuf[p] = j;
        }
    }
    __syncthreads();
    if (t == 0) {
        int na = sm->cnts[0];
        int nt = sm->cnts[1] < TIECAP ? sm->cnts[1] : TIECAP;
        for (int a = 1; a < na; a++) {
            int v = sm->sel[a], p = a - 1;
            while (p >= 0 && sm->sel[p] > v) { sm->sel[p + 1] = sm->sel[p]; p--; }
            sm->sel[p + 1] = v;
        }
        for (int s = 0; s < NKNN - na; s++) {
            int bestv = 1 << 30, bi = 0;
            for (int u = 0; u < nt; u++)
                if (sm->tiebuf[u] < bestv) { bestv = sm->tiebuf[u]; bi = u; }
            sm->sel[na + s] = bestv;
            sm->tiebuf[bi] = 1 << 30;
        }
    }
    __syncthreads();

    if (t < NKNN) {
        int j = sm->sel[t];
        float rx = xi - P[j], ry = yi - P[NPTS + j], rz = zi - P[2 * NPTS + j];
        float acc = 0.0f;
#pragma unroll 8
        for (int o = 0; o < 64; o++) {
            float hp = Wr1[o * 3] * rx + Wr1[o * 3 + 1] * ry + Wr1[o * 3 + 2] * rz + br1[o];
            acc += Wr2[o] * gelu_exact(hp);
        }
        idx_out[(size_t)bq * NKNN + t] = j;
        bias_out[(size_t)bq * NKNN + t] = acc + br2[0];
    }
}

// ---------------- fused proj-GEMM + KNN launch ----------------
__global__ void __launch_bounds__(128) proj_knn_kernel(
        const float* __restrict__ A,
        const ushort_t* __restrict__ Wh, const ushort_t* __restrict__ Wl,
        const float* __restrict__ bias, float* __restrict__ out,
        const float* __restrict__ pos,
        const float* __restrict__ Wr1, const float* __restrict__ br1,
        const float* __restrict__ Wr2, const float* __restrict__ br2,
        int* __restrict__ idx_out, float* __restrict__ bias_out) {
    __shared__ __align__(16) char smraw[FUSED_SMEM];
    int bid = blockIdx.x;
    if (bid < 1024) {
        gemm_body<0>(reinterpret_cast<GemmSmem*>(smraw), bid & 3, bid >> 2,
                     A, Wh, Wl, bias, nullptr, out, 2 * MTOK, CDIM, CDIM);
    } else {
        knn_body(reinterpret_cast<KnnSmem*>(smraw), bid - 1024,
                 pos, Wr1, br1, Wr2, br2, idx_out, bias_out);
    }
}

// ---------------- LayerNorm: warp per row (256 cols), optional residual ----------------
__global__ void ln2_kernel(const float* __restrict__ x, const float* __restrict__ res,
                           const float* __restrict__ g, const float* __restrict__ be,
                           float* __restrict__ out) {
    int warp = threadIdx.x >> 5, lane = threadIdx.x & 31;
    size_t row = (size_t)blockIdx.x * 8 + warp;
    const float* xr = x + row * CDIM;
    float v[8], s = 0.0f, s2 = 0.0f;
#pragma unroll
    for (int i = 0; i < 8; i++) {
        v[i] = xr[i * 32 + lane];
        if (res) v[i] += res[row * CDIM + i * 32 + lane];
        s += v[i]; s2 += v[i] * v[i];
    }
#pragma unroll
    for (int o = 16; o > 0; o >>= 1) {
        s  += __shfl_xor_sync(0xffffffffu, s, o);
        s2 += __shfl_xor_sync(0xffffffffu, s2, o);
    }
    float mean = s * (1.0f / 256.0f);
    float var  = s2 * (1.0f / 256.0f) - mean * mean;
    float rstd = rsqrtf(var + 1e-5f);
#pragma unroll
    for (int i = 0; i < 8; i++)
        out[row * CDIM + i * 32 + lane] = (v[i] - mean) * rstd * g[i * 32 + lane] + be[i * 32 + lane];
}

// ---------------- sparse attention (kv packed: row = [k(256) | v(256)]) ----------------
__global__ void attn_kernel(const float* __restrict__ q, const float* __restrict__ kv,
                            const int* __restrict__ idx, const float* __restrict__ bias,
                            float* __restrict__ out) {
    __shared__ int   sj[NKNN];
    __shared__ float sb[NKNN];
    int m = blockIdx.x;
    int b = m >> 11;
    int warp = threadIdx.x >> 5, lane = threadIdx.x & 31;
    if (threadIdx.x < NKNN) {
        sj[threadIdx.x] = idx[(size_t)m * NKNN + threadIdx.x];
        sb[threadIdx.x] = bias[(size_t)m * NKNN + threadIdx.x];
    }
    __syncthreads();
    int hoff = warp * 64;
    float q0 = q[(size_t)m * CDIM + hoff + lane];
    float q1 = q[(size_t)m * CDIM + hoff + 32 + lane];
    float k0[NKNN], k1[NKNN];
#pragma unroll
    for (int kk = 0; kk < NKNN; kk++) {
        size_t base = ((size_t)b * NPTS + sj[kk]) * 512 + hoff;
        k0[kk] = kv[base + lane];
        k1[kk] = kv[base + 32 + lane];
    }
    float sc[NKNN];
#pragma unroll
    for (int kk = 0; kk < NKNN; kk++) {
        float d = q0 * k0[kk] + q1 * k1[kk];
#pragma unroll
        for (int o = 16; o > 0; o >>= 1) d += __shfl_xor_sync(0xffffffffu, d, o);
        sc[kk] = d * 0.125f + sb[kk];
    }
    float mx = -3.4e38f;
#pragma unroll
    for (int kk = 0; kk < NKNN; kk++) mx = fmaxf(mx, sc[kk]);
    float sum = 0.0f;
#pragma unroll
    for (int kk = 0; kk < NKNN; kk++) { sc[kk] = expf(sc[kk] - mx); sum += sc[kk]; }
    float inv = 1.0f / sum;
#pragma unroll
    for (int kk = 0; kk < NKNN; kk++) {
        size_t base = ((size_t)b * NPTS + sj[kk]) * 512 + 256 + hoff;
        k0[kk] = kv[base + lane];
        k1[kk] = kv[base + 32 + lane];
    }
    float o0 = 0.0f, o1 = 0.0f;
#pragma unroll
    for (int kk = 0; kk < NKNN; kk++) {
        float ww = sc[kk] * inv;
        o0 += ww * k0[kk];
        o1 += ww * k1[kk];
    }
    out[(size_t)m * CDIM + hoff + lane]      = o0;
    out[(size_t)m * CDIM + hoff + 32 + lane] = o1;
}

// ---------------- driver ----------------
extern "C" void kernel_launch(void* const* d_in, const int* in_sizes, int n_in,
                              void* d_out, int out_size) {
    const float* src1 = (const float*)d_in[0];
    const float* src2 = (const float*)d_in[1];
    const float* pos  = (const float*)d_in[2];
    const float* Wp   = (const float*)d_in[3];
    const float* bp   = (const float*)d_in[4];
    const float* Wr1  = (const float*)d_in[5];
    const float* br1  = (const float*)d_in[6];
    const float* Wr2  = (const float*)d_in[7];
    const float* br2  = (const float*)d_in[8];
    const float* Wqkv = (const float*)d_in[9];
    const float* bqkv = (const float*)d_in[10];
    const float* Wo   = (const float*)d_in[11];
    const float* bo   = (const float*)d_in[12];
    const float* g13  = (const float*)d_in[13];
    const float* b13  = (const float*)d_in[14];
    const float* g12  = (const float*)d_in[15];
    const float* b12  = (const float*)d_in[16];
    const float* W1   = (const float*)d_in[17];
    const float* b1   = (const float*)d_in[18];
    const float* W2   = (const float*)d_in[19];
    const float* b2   = (const float*)d_in[20];
    float* out = (float*)d_out;

    float *t, *x, *qb, *kvb, *ao, *tp, *y, *h, *bv;
    ushort_t *wh, *wl;
    int* idxb;
    cudaGetSymbolAddress((void**)&t,  g_t);
    cudaGetSymbolAddress((void**)&x,  g_x);
    cudaGetSymbolAddress((void**)&qb, g_q);
    cudaGetSymbolAddress((void**)&kvb, g_kv);
    cudaGetSymbolAddress((void**)&ao, g_ao);
    cudaGetSymbolAddress((void**)&tp, g_tp);
    cudaGetSymbolAddress((void**)&y,  g_y);
    cudaGetSymbolAddress((void**)&h,  g_h);
    cudaGetSymbolAddress((void**)&wh, g_wh);
    cudaGetSymbolAddress((void**)&wl, g_wl);
    cudaGetSymbolAddress((void**)&bv, g_bv);
    cudaGetSymbolAddress((void**)&idxb, g_idx);

    // fused prep: transpose + weight split
    prep_kernel<<<4096 + (W_TOT + 255) / 256, 256>>>(src1, src2, t, Wp, Wqkv, Wo, W1, W2, wh, wl);

    // fused: input proj (both streams, M = 16384) + KNN/bias
    proj_knn_kernel<<<1024 + MTOK, 128>>>(t, wh + W_P, wl + W_P, bp, x,
                                          pos, Wr1, br1, Wr2, br2, idxb, bv);

    ln2_kernel<<<2 * MTOK / 8, 256>>>(x, nullptr, g13, b13, x);

    // fused Q + KV GEMMs
    qkv_kernel<<<1536, 128>>>(x, wh, wl, bqkv, qb, kvb);

    attn_kernel<<<MTOK, 128>>>(qb, kvb, idxb, bv, ao);

    mma_gemm<0><<<dim3(CDIM / 64, MTOK / 64), 128>>>(ao, wh + W_O, wl + W_O, bo, nullptr, tp, MTOK, CDIM, CDIM);

    ln2_kernel<<<MTOK / 8, 256>>>(x, tp, g12, b12, y);

    mma_gemm<1><<<dim3(DFFN / 64, MTOK / 64), 128>>>(y, wh + W_1, wl + W_1, b1, nullptr, h, MTOK, DFFN, CDIM);
    mma_gemm<2><<<dim3(CDIM / 64, MTOK / 64), 128>>>(h, wh + W_2, wl + W_2, b2, y, out, MTOK, CDIM, DFFN);
}